// round 1
// baseline (speedup 1.0000x reference)
#include <cuda_runtime.h>
#include <math.h>

#define N_NODES  100000
#define N_EDGES  3200000
#define N_GRAPHS 256

// -------- scratch (device globals: no allocations allowed) --------
__device__ int   g_deg[N_NODES];
__device__ float g_dis[N_NODES];
__device__ float g_agg1[N_NODES * 3];
__device__ float g_h1[N_NODES * 32];
__device__ float g_agg2[N_NODES * 32];
__device__ float g_pooled[N_GRAPHS * 64];

// -------- init: zero accumulators, deg=1 (self loop), pooled=-inf --------
__global__ void k_init() {
    int stride = gridDim.x * blockDim.x;
    for (int t = blockIdx.x * blockDim.x + threadIdx.x; t < N_NODES * 32; t += stride) {
        g_agg2[t] = 0.0f;
        if (t < N_NODES)        g_deg[t]  = 1;        // self loop contributes 1
        if (t < N_NODES * 3)    g_agg1[t] = 0.0f;
        if (t < N_GRAPHS * 64)  reinterpret_cast<int*>(g_pooled)[t] = 0xFF800000; // -inf
    }
}

// -------- degree over row endpoints --------
__global__ void k_deg(const int* __restrict__ row) {
    int e = blockIdx.x * blockDim.x + threadIdx.x;
    if (e < N_EDGES) atomicAdd(&g_deg[row[e]], 1);
}

__global__ void k_dis() {
    int i = blockIdx.x * blockDim.x + threadIdx.x;
    if (i < N_NODES) g_dis[i] = rsqrtf((float)g_deg[i]);
}

// -------- layer 1 scatter: agg1[col] += norm * pos[row] (3 feats) --------
__global__ void k_scatter1(const int* __restrict__ row, const int* __restrict__ col,
                           const float* __restrict__ pos) {
    int e = blockIdx.x * blockDim.x + threadIdx.x;
    if (e >= N_EDGES) return;
    int r = row[e], c = col[e];
    float nm = g_dis[r] * g_dis[c];
    atomicAdd(&g_agg1[c * 3 + 0], nm * pos[r * 3 + 0]);
    atomicAdd(&g_agg1[c * 3 + 1], nm * pos[r * 3 + 1]);
    atomicAdd(&g_agg1[c * 3 + 2], nm * pos[r * 3 + 2]);
}

// -------- layer 1 transform: h1 = relu((agg1 + selfloop) @ W1^T + b1), warp per node --------
__global__ void k_transform1(const float* __restrict__ pos,
                             const float* __restrict__ W1,
                             const float* __restrict__ b1) {
    int t = blockIdx.x * blockDim.x + threadIdx.x;
    if (t >= N_NODES * 32) return;
    int i = t >> 5;
    int o = t & 31;
    float di = g_dis[i];
    float s  = di * di;                           // self-loop norm
    float a0 = g_agg1[i * 3 + 0] + s * pos[i * 3 + 0];
    float a1 = g_agg1[i * 3 + 1] + s * pos[i * 3 + 1];
    float a2 = g_agg1[i * 3 + 2] + s * pos[i * 3 + 2];
    float acc = b1[o] + a0 * W1[o * 3 + 0] + a1 * W1[o * 3 + 1] + a2 * W1[o * 3 + 2];
    g_h1[t] = fmaxf(acc, 0.0f);
}

// -------- layer 2 scatter: warp per edge, lane per feature (coalesced) --------
__global__ void k_scatter2(const int* __restrict__ row, const int* __restrict__ col) {
    unsigned t = blockIdx.x * blockDim.x + threadIdx.x;
    if (t >= (unsigned)N_EDGES * 32u) return;
    int e = t >> 5;
    int k = t & 31;
    int r = row[e], c = col[e];
    float nm = g_dis[r] * g_dis[c];               // broadcast loads within warp
    atomicAdd(&g_agg2[c * 32 + k], nm * g_h1[r * 32 + k]);
}

// -------- layer 2 transform + relu + global max pool (fused), 4 nodes/block --------
__global__ void k_transform2_pool(const float* __restrict__ W2,
                                  const float* __restrict__ b2,
                                  const int*   __restrict__ batch,
                                  const float* __restrict__ pos /*unused*/) {
    __shared__ float sW2T[32 * 64];  // [k][o] : transposed for conflict-free LDS
    __shared__ float sA[4 * 32];
    int tid = threadIdx.x;

    for (int x = tid; x < 64 * 32; x += 256) {
        int o = x >> 5, k = x & 31;
        sW2T[k * 64 + o] = W2[x];                 // W2 is [64][32] row-major
    }

    int nd = tid >> 6;        // node slot 0..3
    int o  = tid & 63;        // output feature
    int i  = blockIdx.x * 4 + nd;
    bool valid = (i < N_NODES);

    if (valid && o < 32) {
        float di = g_dis[i];
        float s  = di * di;
        sA[nd * 32 + o] = g_agg2[i * 32 + o] + s * g_h1[i * 32 + o];
    }
    __syncthreads();

    if (valid) {
        float acc = b2[o];
#pragma unroll
        for (int k = 0; k < 32; k++)
            acc = fmaf(sA[nd * 32 + k], sW2T[k * 64 + o], acc);
        acc = fmaxf(acc, 0.0f);
        int g = batch[i];
        // relu output >= 0, init is -inf bits: int-punned atomicMax == float max
        atomicMax(reinterpret_cast<int*>(&g_pooled[g * 64 + o]), __float_as_int(acc));
    }
}

// -------- head: out = pooled @ Wc^T + bc  (256x64 @ 64x2) --------
__global__ void k_final(const float* __restrict__ Wc, const float* __restrict__ bc,
                        float* __restrict__ out) {
    int t = blockIdx.x * blockDim.x + threadIdx.x;
    if (t >= N_GRAPHS * 2) return;
    int g = t >> 1;
    int o = t & 1;
    float acc = bc[o];
#pragma unroll
    for (int k = 0; k < 64; k++)
        acc = fmaf(g_pooled[g * 64 + k], Wc[o * 64 + k], acc);
    out[t] = acc;
}

extern "C" void kernel_launch(void* const* d_in, const int* in_sizes, int n_in,
                              void* d_out, int out_size) {
    const float* pos  = (const float*)d_in[0];
    const int*   eidx = (const int*)  d_in[1];
    const int*   bat  = (const int*)  d_in[2];
    const float* W1   = (const float*)d_in[3];
    const float* b1   = (const float*)d_in[4];
    const float* W2   = (const float*)d_in[5];
    const float* b2   = (const float*)d_in[6];
    const float* Wc   = (const float*)d_in[7];
    const float* bc   = (const float*)d_in[8];
    float* out = (float*)d_out;

    const int* row = eidx;             // edge_index[0]
    const int* col = eidx + N_EDGES;   // edge_index[1]

    const int TB = 256;

    k_init<<<(N_NODES * 32 + TB - 1) / TB, TB>>>();
    k_deg<<<(N_EDGES + TB - 1) / TB, TB>>>(row);
    k_dis<<<(N_NODES + TB - 1) / TB, TB>>>();
    k_scatter1<<<(N_EDGES + TB - 1) / TB, TB>>>(row, col, pos);
    k_transform1<<<(N_NODES * 32 + TB - 1) / TB, TB>>>(pos, W1, b1);
    {
        unsigned total = (unsigned)N_EDGES * 32u;
        k_scatter2<<<(total + TB - 1) / TB, TB>>>(row, col);
    }
    k_transform2_pool<<<(N_NODES + 3) / 4, TB>>>(W2, b2, bat, pos);
    k_final<<<(N_GRAPHS * 2 + TB - 1) / TB, TB>>>(Wc, bc, out);
}

// round 2
// speedup vs baseline: 1.4067x; 1.4067x over previous
#include <cuda_runtime.h>
#include <math.h>

#define N_NODES  100000
#define N_EDGES  3200000
#define N_GRAPHS 256

// -------- scratch (device globals: no allocations allowed) --------
__device__ int   g_deg[N_NODES];
__device__ float g_dis[N_NODES];
__device__ float g_norm[N_EDGES];                       // per-edge dis[r]*dis[c]
__device__ __align__(16) float g_agg1[N_NODES * 4];     // padded to 4 for v4 red
__device__ __align__(16) float g_h1[N_NODES * 32];
__device__ __align__(16) float g_agg2[N_NODES * 32];
__device__ float g_pooled[N_GRAPHS * 64];

// 16B vector reduction (sm_90+): one L2 atomic op for 4 floats
__device__ __forceinline__ void red_add_v4(float* ptr, float a, float b, float c, float d) {
    asm volatile("red.global.add.v4.f32 [%0], {%1, %2, %3, %4};"
                 :: "l"(ptr), "f"(a), "f"(b), "f"(c), "f"(d) : "memory");
}

// -------- init: zero accumulators, deg=1 (self loop), pooled=-inf --------
__global__ void k_init() {
    int stride = gridDim.x * blockDim.x;
    for (int t = blockIdx.x * blockDim.x + threadIdx.x; t < N_NODES * 32; t += stride) {
        g_agg2[t] = 0.0f;
        if (t < N_NODES)        g_deg[t]  = 1;        // self loop contributes 1
        if (t < N_NODES * 4)    g_agg1[t] = 0.0f;
        if (t < N_GRAPHS * 64)  reinterpret_cast<int*>(g_pooled)[t] = 0xFF800000; // -inf
    }
}

// -------- degree over row endpoints --------
__global__ void k_deg(const int* __restrict__ row) {
    int e = blockIdx.x * blockDim.x + threadIdx.x;
    if (e < N_EDGES) atomicAdd(&g_deg[row[e]], 1);
}

__global__ void k_dis() {
    int i = blockIdx.x * blockDim.x + threadIdx.x;
    if (i < N_NODES) g_dis[i] = rsqrtf((float)g_deg[i]);
}

// -------- layer 1 scatter: one v4 red per edge, also materialize norm[e] --------
__global__ void k_scatter1(const int* __restrict__ row, const int* __restrict__ col,
                           const float* __restrict__ pos) {
    int e = blockIdx.x * blockDim.x + threadIdx.x;
    if (e >= N_EDGES) return;
    int r = row[e], c = col[e];
    float nm = g_dis[r] * g_dis[c];
    g_norm[e] = nm;
    float p0 = pos[r * 3 + 0], p1 = pos[r * 3 + 1], p2 = pos[r * 3 + 2];
    red_add_v4(&g_agg1[c * 4], nm * p0, nm * p1, nm * p2, 0.0f);
}

// -------- layer 1 transform: h1 = relu((agg1 + selfloop) @ W1^T + b1), warp per node --------
__global__ void k_transform1(const float* __restrict__ pos,
                             const float* __restrict__ W1,
                             const float* __restrict__ b1) {
    int t = blockIdx.x * blockDim.x + threadIdx.x;
    if (t >= N_NODES * 32) return;
    int i = t >> 5;
    int o = t & 31;
    float di = g_dis[i];
    float s  = di * di;                           // self-loop norm
    float a0 = g_agg1[i * 4 + 0] + s * pos[i * 3 + 0];
    float a1 = g_agg1[i * 4 + 1] + s * pos[i * 3 + 1];
    float a2 = g_agg1[i * 4 + 2] + s * pos[i * 3 + 2];
    float acc = b1[o] + a0 * W1[o * 3 + 0] + a1 * W1[o * 3 + 1] + a2 * W1[o * 3 + 2];
    g_h1[t] = fmaxf(acc, 0.0f);
}

// -------- layer 2 scatter: 8 lanes per edge, one v4 red each --------
__global__ void k_scatter2(const int* __restrict__ row, const int* __restrict__ col) {
    unsigned t = blockIdx.x * blockDim.x + threadIdx.x;
    if (t >= (unsigned)N_EDGES * 8u) return;
    int e = t >> 3;
    int q = t & 7;                               // which float4 of the 32 feats
    int r = row[e], c = col[e];
    float nm = g_norm[e];
    float4 h = *reinterpret_cast<const float4*>(&g_h1[r * 32 + q * 4]);
    red_add_v4(&g_agg2[c * 32 + q * 4], nm * h.x, nm * h.y, nm * h.z, nm * h.w);
}

// -------- layer 2 transform + relu + global max pool (fused), 4 nodes/block --------
__global__ void k_transform2_pool(const float* __restrict__ W2,
                                  const float* __restrict__ b2,
                                  const int*   __restrict__ batch) {
    __shared__ float sW2T[32 * 64];  // [k][o] : transposed for conflict-free LDS
    __shared__ float sA[4 * 32];
    int tid = threadIdx.x;

    for (int x = tid; x < 64 * 32; x += 256) {
        int o = x >> 5, k = x & 31;
        sW2T[k * 64 + o] = W2[x];                 // W2 is [64][32] row-major
    }

    int nd = tid >> 6;        // node slot 0..3
    int o  = tid & 63;        // output feature
    int i  = blockIdx.x * 4 + nd;
    bool valid = (i < N_NODES);

    if (valid && o < 32) {
        float di = g_dis[i];
        float s  = di * di;
        sA[nd * 32 + o] = g_agg2[i * 32 + o] + s * g_h1[i * 32 + o];
    }
    __syncthreads();

    if (valid) {
        float acc = b2[o];
#pragma unroll
        for (int k = 0; k < 32; k++)
            acc = fmaf(sA[nd * 32 + k], sW2T[k * 64 + o], acc);
        acc = fmaxf(acc, 0.0f);
        int g = batch[i];
        // relu output >= 0, init is -inf bits: int-punned atomicMax == float max
        atomicMax(reinterpret_cast<int*>(&g_pooled[g * 64 + o]), __float_as_int(acc));
    }
}

// -------- head: out = pooled @ Wc^T + bc  (256x64 @ 64x2) --------
__global__ void k_final(const float* __restrict__ Wc, const float* __restrict__ bc,
                        float* __restrict__ out) {
    int t = blockIdx.x * blockDim.x + threadIdx.x;
    if (t >= N_GRAPHS * 2) return;
    int g = t >> 1;
    int o = t & 1;
    float acc = bc[o];
#pragma unroll
    for (int k = 0; k < 64; k++)
        acc = fmaf(g_pooled[g * 64 + k], Wc[o * 64 + k], acc);
    out[t] = acc;
}

extern "C" void kernel_launch(void* const* d_in, const int* in_sizes, int n_in,
                              void* d_out, int out_size) {
    const float* pos  = (const float*)d_in[0];
    const int*   eidx = (const int*)  d_in[1];
    const int*   bat  = (const int*)  d_in[2];
    const float* W1   = (const float*)d_in[3];
    const float* b1   = (const float*)d_in[4];
    const float* W2   = (const float*)d_in[5];
    const float* b2   = (const float*)d_in[6];
    const float* Wc   = (const float*)d_in[7];
    const float* bc   = (const float*)d_in[8];
    float* out = (float*)d_out;

    const int* row = eidx;             // edge_index[0]
    const int* col = eidx + N_EDGES;   // edge_index[1]

    const int TB = 256;

    k_init<<<(N_NODES * 32 + TB - 1) / TB, TB>>>();
    k_deg<<<(N_EDGES + TB - 1) / TB, TB>>>(row);
    k_dis<<<(N_NODES + TB - 1) / TB, TB>>>();
    k_scatter1<<<(N_EDGES + TB - 1) / TB, TB>>>(row, col, pos);
    k_transform1<<<(N_NODES * 32 + TB - 1) / TB, TB>>>(pos, W1, b1);
    {
        unsigned total = (unsigned)N_EDGES * 8u;
        k_scatter2<<<(total + TB - 1) / TB, TB>>>(row, col);
    }
    k_transform2_pool<<<(N_NODES + 3) / 4, TB>>>(W2, b2, bat);
    k_final<<<(N_GRAPHS * 2 + TB - 1) / TB, TB>>>(Wc, bc, out);
}

// round 3
// speedup vs baseline: 2.5123x; 1.7860x over previous
#include <cuda_runtime.h>
#include <math.h>

#define N_NODES  100000
#define N_EDGES  3200000
#define N_GRAPHS 256

// -------- scratch (device globals: no allocations allowed) --------
__device__ int   g_deg[N_NODES];
__device__ float g_dis[N_NODES];
__device__ float g_norm[N_EDGES];
__device__ __align__(16) float g_ps[N_NODES * 4];    // {d*p0, d*p1, d*p2, d}
__device__ __align__(16) float g_agg1[N_NODES * 4];  // seeded with self-loop d^2*pos
__device__ __align__(16) float g_h1[N_NODES * 32];
__device__ __align__(16) float g_agg2[N_NODES * 32]; // seeded with self-loop d^2*h1
__device__ float g_pooled[N_GRAPHS * 64];

__device__ __forceinline__ void red_add_v4(float* p, float a, float b, float c, float d) {
    asm volatile("red.global.add.v4.f32 [%0], {%1, %2, %3, %4};"
                 :: "l"(p), "f"(a), "f"(b), "f"(c), "f"(d) : "memory");
}
__device__ __forceinline__ void red_add_s32(int* p, int v) {
    asm volatile("red.global.add.s32 [%0], %1;" :: "l"(p), "r"(v) : "memory");
}

// -------- init: deg=1 (self loop), pooled=-inf (tiny) --------
__global__ void k_init() {
    int t = blockIdx.x * blockDim.x + threadIdx.x;
    if (t < N_NODES) g_deg[t] = 1;
    if (t < N_GRAPHS * 64) reinterpret_cast<int*>(g_pooled)[t] = 0xFF800000;
}

// -------- degree: int4 row loads, 4 non-returning reds per thread --------
__global__ void k_deg(const int4* __restrict__ row4) {
    int t = blockIdx.x * blockDim.x + threadIdx.x;
    if (t >= N_EDGES / 4) return;
    int4 r = row4[t];
    red_add_s32(&g_deg[r.x], 1);
    red_add_s32(&g_deg[r.y], 1);
    red_add_s32(&g_deg[r.z], 1);
    red_add_s32(&g_deg[r.w], 1);
}

// -------- dis + pos_scaled + agg1 self-loop seed --------
__global__ void k_dis(const float* __restrict__ pos) {
    int i = blockIdx.x * blockDim.x + threadIdx.x;
    if (i >= N_NODES) return;
    float d = rsqrtf((float)g_deg[i]);
    g_dis[i] = d;
    float p0 = pos[i * 3 + 0], p1 = pos[i * 3 + 1], p2 = pos[i * 3 + 2];
    *reinterpret_cast<float4*>(&g_ps[i * 4])   = make_float4(d * p0, d * p1, d * p2, d);
    float s = d * d;
    *reinterpret_cast<float4*>(&g_agg1[i * 4]) = make_float4(s * p0, s * p1, s * p2, 0.0f);
}

// -------- layer 1 scatter: 2 gathers (16B ps[r], 4B dis[c]) + 1 red per edge --------
__global__ void k_scatter1(const int* __restrict__ row, const int* __restrict__ col) {
    int e = blockIdx.x * blockDim.x + threadIdx.x;
    if (e >= N_EDGES) return;
    int r = row[e], c = col[e];
    float4 ps = *reinterpret_cast<const float4*>(&g_ps[r * 4]);
    float dc = g_dis[c];
    g_norm[e] = ps.w * dc;
    red_add_v4(&g_agg1[c * 4], dc * ps.x, dc * ps.y, dc * ps.z, 0.0f);
}

// -------- layer 1 transform: h1 + agg2 self-loop seed, warp per node --------
__global__ void k_transform1(const float* __restrict__ W1, const float* __restrict__ b1) {
    int t = blockIdx.x * blockDim.x + threadIdx.x;
    if (t >= N_NODES * 32) return;
    int i = t >> 5;
    int o = t & 31;
    float4 a = *reinterpret_cast<const float4*>(&g_agg1[i * 4]);
    float acc = b1[o] + a.x * W1[o * 3 + 0] + a.y * W1[o * 3 + 1] + a.z * W1[o * 3 + 2];
    float h = fmaxf(acc, 0.0f);
    g_h1[t] = h;
    float d = g_dis[i];
    g_agg2[t] = d * d * h;     // self-loop contribution pre-seeded
}

// -------- layer 2 scatter: 8 lanes per edge, one v4 red each --------
__global__ void k_scatter2(const int* __restrict__ row, const int* __restrict__ col) {
    unsigned t = blockIdx.x * blockDim.x + threadIdx.x;
    if (t >= (unsigned)N_EDGES * 8u) return;
    int e = t >> 3;
    int q = t & 7;
    int r = row[e], c = col[e];
    float nm = g_norm[e];
    float4 h = *reinterpret_cast<const float4*>(&g_h1[r * 32 + q * 4]);
    red_add_v4(&g_agg2[c * 32 + q * 4], nm * h.x, nm * h.y, nm * h.z, nm * h.w);
}

// -------- layer 2 transform + relu + pooled max (register running-max, 32 nodes/block) --------
#define NPB 32
__global__ void k_transform2_pool(const float* __restrict__ W2,
                                  const float* __restrict__ b2,
                                  const int*   __restrict__ batch) {
    __shared__ float sW2T[32 * 64];     // [k][o] transposed
    __shared__ float sA[2][4 * 32];     // double buffer: 4 nodes x 32 feats
    int tid = threadIdx.x;

    for (int x = tid; x < 64 * 32; x += 256) {
        int o = x >> 5, k = x & 31;
        sW2T[k * 64 + o] = W2[x];       // W2 is [64][32] row-major
    }

    int nd = tid >> 6;                  // node slot 0..3
    int o  = tid & 63;                  // output feature
    int base = blockIdx.x * NPB;
    float bo = b2[o];

    int   curg = -1;
    float gmax = 0.0f;                  // relu output >= 0, so 0 is a safe identity

#pragma unroll
    for (int j = 0; j < NPB / 4; j++) {
        int i = base + j * 4 + nd;
        int buf = j & 1;
        if (o < 32 && i < N_NODES)
            sA[buf][nd * 32 + o] = g_agg2[i * 32 + o];
        __syncthreads();
        if (i < N_NODES) {
            float acc = bo;
#pragma unroll
            for (int k = 0; k < 32; k++)
                acc = fmaf(sA[buf][nd * 32 + k], sW2T[k * 64 + o], acc);
            acc = fmaxf(acc, 0.0f);
            int g = batch[i];
            if (g != curg) {
                if (curg >= 0)
                    atomicMax(reinterpret_cast<int*>(&g_pooled[curg * 64 + o]),
                              __float_as_int(gmax));
                curg = g;
                gmax = acc;
            } else {
                gmax = fmaxf(gmax, acc);
            }
        }
    }
    if (curg >= 0)
        atomicMax(reinterpret_cast<int*>(&g_pooled[curg * 64 + o]),
                  __float_as_int(gmax));
}

// -------- head: out = pooled @ Wc^T + bc  (256x64 @ 64x2) --------
__global__ void k_final(const float* __restrict__ Wc, const float* __restrict__ bc,
                        float* __restrict__ out) {
    int t = blockIdx.x * blockDim.x + threadIdx.x;
    if (t >= N_GRAPHS * 2) return;
    int g = t >> 1;
    int o = t & 1;
    float acc = bc[o];
#pragma unroll
    for (int k = 0; k < 64; k++)
        acc = fmaf(g_pooled[g * 64 + k], Wc[o * 64 + k], acc);
    out[t] = acc;
}

extern "C" void kernel_launch(void* const* d_in, const int* in_sizes, int n_in,
                              void* d_out, int out_size) {
    const float* pos  = (const float*)d_in[0];
    const int*   eidx = (const int*)  d_in[1];
    const int*   bat  = (const int*)  d_in[2];
    const float* W1   = (const float*)d_in[3];
    const float* b1   = (const float*)d_in[4];
    const float* W2   = (const float*)d_in[5];
    const float* b2   = (const float*)d_in[6];
    const float* Wc   = (const float*)d_in[7];
    const float* bc   = (const float*)d_in[8];
    float* out = (float*)d_out;

    const int* row = eidx;             // edge_index[0]
    const int* col = eidx + N_EDGES;   // edge_index[1]

    const int TB = 256;

    k_init<<<(N_NODES + TB - 1) / TB, TB>>>();
    k_deg<<<(N_EDGES / 4 + TB - 1) / TB, TB>>>((const int4*)row);
    k_dis<<<(N_NODES + TB - 1) / TB, TB>>>(pos);
    k_scatter1<<<(N_EDGES + TB - 1) / TB, TB>>>(row, col);
    k_transform1<<<(N_NODES * 32 + TB - 1) / TB, TB>>>(W1, b1);
    {
        unsigned total = (unsigned)N_EDGES * 8u;
        k_scatter2<<<(total + TB - 1) / TB, TB>>>(row, col);
    }
    k_transform2_pool<<<(N_NODES + NPB - 1) / NPB, TB>>>(W2, b2, bat);
    k_final<<<(N_GRAPHS * 2 + TB - 1) / TB, TB>>>(Wc, bc, out);
}